// round 12
// baseline (speedup 1.0000x reference)
#include <cuda_runtime.h>
#include <cuda_bf16.h>
#include <cstdint>
#include <cstddef>

typedef unsigned int u32;
typedef unsigned long long u64;

#define TT 256
#define NB 64            /* barrier quorum per direction */

// ---- scan smem layout (bytes) ----
#define HS_OFF 0          /* h stacked hi/lo: 128 rows x 520 bf16 (1040 B/row) */
#define BH_OFF 133120     /* R_hi: 32 rows([n]) x 520 bf16 */
#define BL_OFF 166400
#define ZB_OFF 199680     /* z: 128 x 36 f32 */
#define MB_OFF 218112     /* mask bitmap: 512 u32 */
#define XZ_OFF 220160     /* xz tile: 64 x 36 f32 (144 B/row) */
#define SM_SCAN 229376

// ---- xproj smem layout ----
#define AH_OFF 0          /* A hi: 128 rows x 264 bf16 (528 B/row) */
#define AL_OFF 67584
#define WH_OFF 135168     /* W hi: 64 rows([n]) x 264 bf16 */
#define WL_OFF 168960
#define BIAS_OFF 202752
#define TOKS_OFF 203776
#define SM_XP 204800

// Device-global scratch (allocation-guard safe)
__device__ float          g_xq[(size_t)2 * 64 * TT * 64 * 32]; // [dir][ug][t][b][g*8+u]
__device__ __nv_bfloat16  g_hbf[2 * 2 * 128 * 512];            // [par][dir][hi0-63|lo64-127][512]
__device__ unsigned       g_bar2[2][TT];

__device__ __forceinline__ u32 smem_u32(const void* p) {
    u32 a;
    asm("{ .reg .u64 t; cvta.to.shared.u64 t, %1; cvt.u32.u64 %0, t; }" : "=r"(a) : "l"(p));
    return a;
}
__device__ __forceinline__ u32 packbf(float a, float b) {
    __nv_bfloat162 t = __floats2bfloat162_rn(a, b);
    return *reinterpret_cast<u32*>(&t);
}

#define MMA(d, a, b0_, b1_) \
    asm volatile( \
        "mma.sync.aligned.m16n8k16.row.col.f32.bf16.bf16.f32 " \
        "{%0,%1,%2,%3},{%4,%5,%6,%7},{%8,%9},{%0,%1,%2,%3};" \
        : "+f"((d)[0]), "+f"((d)[1]), "+f"((d)[2]), "+f"((d)[3]) \
        : "r"((a)[0]), "r"((a)[1]), "r"((a)[2]), "r"((a)[3]), \
          "r"(b0_), "r"(b1_))

#define LDSM4(r, a) \
    asm volatile("ldmatrix.sync.aligned.m8n8.x4.shared.b16 {%0,%1,%2,%3}, [%4];" \
        : "=r"((r)[0]), "=r"((r)[1]), "=r"((r)[2]), "=r"((r)[3]) : "r"(a))

#define CP_ASYNC16(dst, src) \
    asm volatile("cp.async.cg.shared.global [%0], [%1], 16;" :: "r"(dst), "l"(src))
#define CP_COMMIT() asm volatile("cp.async.commit_group;" ::: "memory")
#define CP_WAIT(n)  asm volatile("cp.async.wait_group %0;" :: "n"(n) : "memory")

// ---------------------------------------------------------------------------
// Fused x_proj: emb gather + bf16 hi/lo convert + 3-product GEMM.
// CTA: 128 rows x 256 cols; writes PERMUTED layout g_xq[dir][ug][t][b][32].
// ---------------------------------------------------------------------------
__global__ void __launch_bounds__(128, 1) xproj_kernel(
    const int* __restrict__ x, const float* __restrict__ emb,
    const float* __restrict__ W_f, const float* __restrict__ b_f,
    const float* __restrict__ W_b, const float* __restrict__ b_b)
{
    extern __shared__ char sp[];
    const int tid = threadIdx.x;
    const int warp = tid >> 5, lane = tid & 31;
    const int qr = lane >> 2, qc = lane & 3;
    const int dir = blockIdx.z;
    const int m0  = blockIdx.y << 7;
    const int ng  = blockIdx.x;
    const float* Wm = dir ? W_b : W_f;
    const float* bs = dir ? b_b : b_f;
    float* sbias = (float*)(sp + BIAS_OFF);
    int*   toks  = (int*)(sp + TOKS_OFF);

    {
        int r = m0 + tid;
        toks[tid] = x[(r & 63) * TT + (r >> 6)];
    }
    for (int i = tid; i < 256; i += 128) sbias[i] = bs[(ng << 8) + i];
    __syncthreads();

    // A gather + hi/lo convert into [128][528] bf16 (proven in R6)
    #pragma unroll 4
    for (int it = 0; it < 32; it++) {
        int c = (it << 7) + tid;
        int row = c >> 5, q = c & 31;
        const float* e = emb + (size_t)toks[row] * 256 + (q << 3);
        float4 v0 = *(const float4*)e;
        float4 v1 = *(const float4*)(e + 4);
        float a[8] = {v0.x, v0.y, v0.z, v0.w, v1.x, v1.y, v1.z, v1.w};
        u32 hi[4], lo[4];
        #pragma unroll
        for (int p = 0; p < 4; p++) {
            float x0 = a[2 * p], x1 = a[2 * p + 1];
            __nv_bfloat16 h0 = __float2bfloat16(x0), h1 = __float2bfloat16(x1);
            hi[p] = ((u32)*(unsigned short*)&h1 << 16) | *(unsigned short*)&h0;
            lo[p] = packbf(x0 - __bfloat162float(h0), x1 - __bfloat162float(h1));
        }
        *(uint4*)(sp + AH_OFF + row * 528 + q * 16) = make_uint4(hi[0], hi[1], hi[2], hi[3]);
        *(uint4*)(sp + AL_OFF + row * 528 + q * 16) = make_uint4(lo[0], lo[1], lo[2], lo[3]);
    }

    const u32 spb = smem_u32(sp);
    u32 aAh[2], aAl[2];
    #pragma unroll
    for (int mi = 0; mi < 2; mi++) {
        int row = (warp << 5) + (mi << 4) + (lane & 15);
        aAh[mi] = spb + AH_OFF + row * 528 + (lane >> 4) * 16;
        aAl[mi] = spb + AL_OFF + row * 528 + (lane >> 4) * 16;
    }
    const int brow = (lane & 7) + 8 * (lane >> 4);
    const u32 koff = ((lane >> 3) & 1) * 16;
    const int gph = ng >> 1;             // gate of this 256-col group
    const int ubase = (ng & 1) << 8;     // unit base 0 / 256

    for (int nt = 0; nt < 4; nt++) {
        const int ncol0 = (ng << 8) + (nt << 6);
        __syncthreads();
        // W tile convert: [64][528] bf16 hi/lo
        for (int i = tid; i < 64 * 256; i += 128) {
            int n = i & 63, k = i >> 6;
            float v = Wm[(size_t)k * 2048 + ncol0 + n];
            __nv_bfloat16 hb = __float2bfloat16(v);
            *(__nv_bfloat16*)(sp + WH_OFF + n * 528 + k * 2) = hb;
            *(__nv_bfloat16*)(sp + WL_OFF + n * 528 + k * 2) =
                __float2bfloat16(v - __bfloat162float(hb));
        }
        __syncthreads();

        float acc[2][8][4] = {};
        #pragma unroll 1
        for (int kk = 0; kk < 16; kk++) {
            u32 ah[2][4], al[2][4];
            LDSM4(ah[0], aAh[0] + kk * 32);
            LDSM4(ah[1], aAh[1] + kk * 32);
            LDSM4(al[0], aAl[0] + kk * 32);
            LDSM4(al[1], aAl[1] + kk * 32);
            #pragma unroll
            for (int p = 0; p < 4; p++) {
                u32 bh[4], bl[4];
                u32 ab = spb + (brow + (p << 4)) * 528 + koff + kk * 32;
                LDSM4(bh, ab + WH_OFF);
                LDSM4(bl, ab + WL_OFF);
                #pragma unroll
                for (int q = 0; q < 2; q++) {
                    int ni = (p << 1) + q;
                    #pragma unroll
                    for (int mi = 0; mi < 2; mi++) {
                        MMA(acc[mi][ni], ah[mi], bh[2 * q], bh[2 * q + 1]);
                        MMA(acc[mi][ni], ah[mi], bl[2 * q], bl[2 * q + 1]);
                        MMA(acc[mi][ni], al[mi], bh[2 * q], bh[2 * q + 1]);
                    }
                }
            }
        }

        // Permuted epilogue: addr = (((dir*64+ug)*256 + t)*64 + b)*32 + g*8 + uu
        #pragma unroll
        for (int mi = 0; mi < 2; mi++) {
            int rl = (warp << 5) + (mi << 4) + qr;
            int r0 = m0 + rl, r1 = r0 + 8;
            int t0 = r0 >> 6, b0v = r0 & 63;
            int t1 = r1 >> 6, b1v = r1 & 63;
            #pragma unroll
            for (int ni = 0; ni < 8; ni++) {
                int cl = (nt << 6) + (ni << 3) + (qc << 1);
                int up = ubase + cl;
                float bb0 = sbias[cl], bb1 = sbias[cl + 1];
                size_t blk = ((size_t)(dir * 64 + (up >> 3)));
                size_t a0 = ((blk * 256 + t0) * 64 + b0v) * 32 + gph * 8 + (up & 7);
                size_t a1 = ((blk * 256 + t1) * 64 + b1v) * 32 + gph * 8 + (up & 7);
                *(float2*)(g_xq + a0) = make_float2(acc[mi][ni][0] + bb0, acc[mi][ni][1] + bb1);
                *(float2*)(g_xq + a1) = make_float2(acc[mi][ni][2] + bb0, acc[mi][ni][3] + bb1);
            }
        }
    }
}

// ---------------------------------------------------------------------------
// Persistent bidirectional LSTM scan. 128 CTAs x 256 thr (8 warps).
// Per-direction 64-CTA barriers; xz prefetched one step ahead via cp.async;
// h restage overlapped with 3-product hi/lo MMA.
// ---------------------------------------------------------------------------
__global__ void __launch_bounds__(256, 1) scan_kernel(
    const int* __restrict__ x,
    const float* __restrict__ R_f,
    const float* __restrict__ R_b,
    float* __restrict__ out)
{
    extern __shared__ char sp[];
    const int tid = threadIdx.x;
    const int warp = tid >> 5, lane = tid & 31;
    const int qr = lane >> 2, qc = lane & 3;
    const int dir = blockIdx.x >> 6;
    const int ug  = blockIdx.x & 63;
    const int u0  = ug << 3;
    const float* Rm = dir ? R_b : R_f;
    float* zr = (float*)(sp + ZB_OFF);
    u32* mbits = (u32*)(sp + MB_OFF);
    float* xzs = (float*)(sp + XZ_OFF);            // [64][36] f32

    // Persistent B: row n <- R[:, (n&3)*512 + u0 + (n>>2)], hi/lo split
    for (int i = tid; i < 32 * 512; i += 256) {
        int n = i & 31, k = i >> 5;
        float v = Rm[(size_t)k * 2048 + (n & 3) * 512 + u0 + (n >> 2)];
        __nv_bfloat16 hb = __float2bfloat16(v);
        *(__nv_bfloat16*)(sp + BH_OFF + n * 1040 + k * 2) = hb;
        *(__nv_bfloat16*)(sp + BL_OFF + n * 1040 + k * 2) =
            __float2bfloat16(v - __bfloat162float(hb));
    }
    // Mask bitmap: word w = t*2 + (b>>5)
    for (int w = tid; w < 512; w += 256) {
        int t = w >> 1, h32 = (w & 1) << 5;
        u32 bits = 0;
        #pragma unroll 8
        for (int j = 0; j < 32; j++)
            bits |= (u32)(x[(h32 + j) * TT + t] != 0) << j;
        mbits[w] = bits;
    }

    const u32 spb = smem_u32(sp);
    const char* xqbase = (const char*)(g_xq + (size_t)(dir * 64 + ug) * TT * 64 * 32);

    // Prefetch xz for s=0
    {
        int t0 = dir ? (TT - 1) : 0;
        const char* src = xqbase + (size_t)t0 * 8192;
        #pragma unroll
        for (int it = 0; it < 2; it++) {
            int c = (it << 8) + tid;               // 0..511
            CP_ASYNC16(spb + XZ_OFF + (c >> 3) * 144 + (c & 7) * 16, src + c * 16);
        }
        CP_COMMIT();
    }

    const u32 aA = spb + HS_OFF + ((warp << 4) + (lane & 15)) * 1040 + (lane >> 4) * 16;
    const int brow = (lane & 7) + 8 * (lane >> 4);
    const u32 koff = ((lane >> 3) & 1) * 16;
    const bool heavy = warp < 4;      // hh rows: also multiply by R_lo

    const int ue = tid & 3;           // unit pair: units 2ue, 2ue+1
    const int be = tid >> 2;          // batch 0..63
    float cst[2] = {0.f, 0.f}, hcur[2] = {0.f, 0.f};
    unsigned* mybar = &g_bar2[dir][0];

    __syncthreads();

    for (int s = 0; s < TT; s++) {
        const int t = dir ? (TT - 1 - s) : s;
        const int m = (mbits[(t << 1) + (be >> 5)] >> (be & 31)) & 1;

        if (s) {
            // cp.async restage of A=[h_hi;h_lo]: two k-halves, 64 KB each
            const char* hb = (const char*)(g_hbf +
                ((size_t)(((s - 1) & 1) * 2 + dir) * 128) * 512);
            #pragma unroll
            for (int half = 0; half < 2; half++) {
                #pragma unroll
                for (int it = 0; it < 16; it++) {
                    int idx = (it << 8) + tid;
                    int row = idx >> 5;
                    int c = (half << 5) + (idx & 31);
                    CP_ASYNC16(spb + HS_OFF + row * 1040 + c * 16,
                               hb + row * 1024 + c * 16);
                }
                CP_COMMIT();
            }

            float acc[4][4] = {};
            #pragma unroll
            for (int half = 0; half < 2; half++) {
                if (half == 0) CP_WAIT(1); else CP_WAIT(0);
                __syncthreads();
                #pragma unroll 2
                for (int kk = half << 4; kk < (half + 1) << 4; kk++) {
                    u32 a[4];
                    LDSM4(a, aA + kk * 32);
                    #pragma unroll
                    for (int p = 0; p < 2; p++) {
                        u32 bh[4];
                        u32 ab = spb + (brow + (p << 4)) * 1040 + koff + kk * 32;
                        LDSM4(bh, ab + BH_OFF);
                        MMA(acc[(p << 1) + 0], a, bh[0], bh[1]);
                        MMA(acc[(p << 1) + 1], a, bh[2], bh[3]);
                        if (heavy) {
                            u32 bl[4];
                            LDSM4(bl, ab + BL_OFF);
                            MMA(acc[(p << 1) + 0], a, bl[0], bl[1]);
                            MMA(acc[(p << 1) + 1], a, bl[2], bl[3]);
                        }
                    }
                }
            }
            {
                int row0 = (warp << 4) + qr;
                #pragma unroll
                for (int ni = 0; ni < 4; ni++) {
                    int col = (ni << 3) + (qc << 1);
                    *(float2*)(zr + row0 * 36 + col) = make_float2(acc[ni][0], acc[ni][1]);
                    *(float2*)(zr + (row0 + 8) * 36 + col) = make_float2(acc[ni][2], acc[ni][3]);
                }
            }
            __syncthreads();
        } else {
            CP_WAIT(0);
            __syncthreads();
        }

        float h2[2];
        #pragma unroll
        for (int j = 0; j < 2; j++) {
            int cb = ((ue << 1) + j) << 2;
            const float* xrow = xzs + be * 36;
            float zi = xrow[(ue << 1) + j];
            float zf = xrow[8 + (ue << 1) + j];
            float zg = xrow[16 + (ue << 1) + j];
            float zo = xrow[24 + (ue << 1) + j];
            if (s) {
                float4 vh = *(const float4*)(zr + be * 36 + cb);
                float4 vl = *(const float4*)(zr + (64 + be) * 36 + cb);
                zi += vh.x + vl.x; zf += vh.y + vl.y;
                zg += vh.z + vl.z; zo += vh.w + vl.w;
            }
            float iv = tanhf(zi), fv = tanhf(zf), gv = tanhf(zg), ov = tanhf(zo);
            float cn = fv * cst[j] + iv * gv;
            float hn = ov * tanhf(cn);
            if (m) { cst[j] = cn; hcur[j] = hn; }
            h2[j] = hcur[j];
        }

        *(float2*)(out + (((size_t)(be * TT + t)) << 10) + (dir << 9) + u0 + (ue << 1)) =
            make_float2(h2[0], h2[1]);
        if (dir && s == TT - 1)
            *(float2*)(out + (size_t)64 * TT * 1024 + (size_t)be * 512 + u0 + (ue << 1)) =
                make_float2(h2[0], h2[1]);
        {
            __nv_bfloat16 b0 = __float2bfloat16(h2[0]), b1 = __float2bfloat16(h2[1]);
            u32 hiw = ((u32)*(unsigned short*)&b1 << 16) | *(unsigned short*)&b0;
            u32 low = packbf(h2[0] - __bfloat162float(b0), h2[1] - __bfloat162float(b1));
            __nv_bfloat16* hb = g_hbf + ((size_t)((s & 1) * 2 + dir) * 128) * 512;
            *(u32*)(hb + (size_t)be * 512 + u0 + (ue << 1))        = hiw;
            *(u32*)(hb + (size_t)(64 + be) * 512 + u0 + (ue << 1)) = low;
        }

        __syncthreads();   // XZ/zr reads complete before prefetch overwrite
        if (s < TT - 1) {
            // Prefetch xz(s+1) — overlaps barrier wait + next restage + MMA
            {
                int tn = dir ? (TT - 2 - s) : (s + 1);
                const char* src = xqbase + (size_t)tn * 8192;
                #pragma unroll
                for (int it = 0; it < 2; it++) {
                    int c = (it << 8) + tid;
                    CP_ASYNC16(spb + XZ_OFF + (c >> 3) * 144 + (c & 7) * 16, src + c * 16);
                }
                CP_COMMIT();
            }
            if (tid == 0) {
                asm volatile("red.release.gpu.add.u32 [%0], 1;" :: "l"(mybar + s) : "memory");
                unsigned cnt;
                do {
                    asm volatile("ld.acquire.gpu.u32 %0, [%1];"
                                 : "=r"(cnt) : "l"(mybar + s) : "memory");
                } while (cnt < NB);
            }
            __syncthreads();
        }
    }

    // Self-reset this direction's barrier array for the next replay.
    __syncthreads();
    if (tid == 0) {
        asm volatile("red.release.gpu.add.u32 [%0], 1;" :: "l"(mybar + TT - 1) : "memory");
        if (ug == 0) {
            unsigned cnt;
            do {
                asm volatile("ld.acquire.gpu.u32 %0, [%1];"
                             : "=r"(cnt) : "l"(mybar + TT - 1) : "memory");
            } while (cnt < NB);
            for (int i = 0; i < TT; i++) mybar[i] = 0u;
        }
    }
}

extern "C" void kernel_launch(void* const* d_in, const int* in_sizes, int n_in,
                              void* d_out, int out_size) {
    const int*   x   = (const int*)d_in[0];
    const float* emb = (const float*)d_in[1];
    const float* W_f = (const float*)d_in[2];
    const float* R_f = (const float*)d_in[3];
    const float* b_f = (const float*)d_in[4];
    const float* W_b = (const float*)d_in[5];
    const float* R_b = (const float*)d_in[6];
    const float* b_b = (const float*)d_in[7];
    float* out = (float*)d_out;

    cudaFuncSetAttribute(xproj_kernel, cudaFuncAttributeMaxDynamicSharedMemorySize, SM_XP);
    cudaFuncSetAttribute(scan_kernel,  cudaFuncAttributeMaxDynamicSharedMemorySize, SM_SCAN);

    xproj_kernel<<<dim3(8, 128, 2), 128, SM_XP>>>(x, emb, W_f, b_f, W_b, b_b);
    scan_kernel<<<128, 256, SM_SCAN>>>(x, R_f, R_b, out);
}

// round 14
// speedup vs baseline: 1.6639x; 1.6639x over previous
#include <cuda_runtime.h>
#include <cuda_bf16.h>
#include <cuda_fp16.h>
#include <cstdint>
#include <cstddef>

typedef unsigned int u32;
typedef unsigned long long u64;

#define TT 256
#define NB 64            /* barrier quorum per direction */

// ---- scan smem layout (bytes) ----
#define HS_OFF 0          /* h fp16: 64 rows x 520 (1040 B/row) */
#define BH_OFF 66560      /* R_hi fp16: 32 n-rows x 520 */
#define BL_OFF 99840      /* R_lo fp16 (x2^11): 32 n-rows x 520 */
#define ZB_OFF 133120     /* z partials: 2 khalf x 64 x 36 f32 */
#define MB_OFF 151552     /* mask bitmap: 512 u32 */
#define SM_SCAN 153600

// ---- xproj smem layout ----
#define AH_OFF 0          /* A hi: 128 rows x 264 bf16 (528 B/row) */
#define AL_OFF 67584
#define WH_OFF 135168     /* W hi: 64 rows([n]) x 264 bf16 */
#define WL_OFF 168960
#define BIAS_OFF 202752
#define SM_XP 204800

// Device-global scratch (allocation-guard safe)
__device__ float          g_xproj[(size_t)2 * TT * 64 * 2048];  // [dir][t*64+b][2048]
__device__ __nv_bfloat16  g_Ah[(size_t)16384 * 256];            // emb gather hi
__device__ __nv_bfloat16  g_Al[(size_t)16384 * 256];
__device__ __nv_bfloat16  g_Wth[(size_t)2 * 2048 * 256];        // W^T hi: [dir][n][k]
__device__ __nv_bfloat16  g_Wtl[(size_t)2 * 2048 * 256];
__device__ __half         g_hf16[2 * 2 * 64 * 512];             // [par][dir][b][u] fp16
__device__ unsigned       g_bar2[2][TT];

__device__ __forceinline__ u32 smem_u32(const void* p) {
    u32 a;
    asm("{ .reg .u64 t; cvta.to.shared.u64 t, %1; cvt.u32.u64 %0, t; }" : "=r"(a) : "l"(p));
    return a;
}
__device__ __forceinline__ u32 packbf(float a, float b) {
    __nv_bfloat162 t = __floats2bfloat162_rn(a, b);
    return *reinterpret_cast<u32*>(&t);
}

#define MMABF(d, a, b0_, b1_) \
    asm volatile( \
        "mma.sync.aligned.m16n8k16.row.col.f32.bf16.bf16.f32 " \
        "{%0,%1,%2,%3},{%4,%5,%6,%7},{%8,%9},{%0,%1,%2,%3};" \
        : "+f"((d)[0]), "+f"((d)[1]), "+f"((d)[2]), "+f"((d)[3]) \
        : "r"((a)[0]), "r"((a)[1]), "r"((a)[2]), "r"((a)[3]), \
          "r"(b0_), "r"(b1_))

#define MMAF16(d, a, b0_, b1_) \
    asm volatile( \
        "mma.sync.aligned.m16n8k16.row.col.f32.f16.f16.f32 " \
        "{%0,%1,%2,%3},{%4,%5,%6,%7},{%8,%9},{%0,%1,%2,%3};" \
        : "+f"((d)[0]), "+f"((d)[1]), "+f"((d)[2]), "+f"((d)[3]) \
        : "r"((a)[0]), "r"((a)[1]), "r"((a)[2]), "r"((a)[3]), \
          "r"(b0_), "r"(b1_))

#define LDSM4(r, a) \
    asm volatile("ldmatrix.sync.aligned.m8n8.x4.shared.b16 {%0,%1,%2,%3}, [%4];" \
        : "=r"((r)[0]), "=r"((r)[1]), "=r"((r)[2]), "=r"((r)[3]) : "r"(a))

#define CP_ASYNC16(dst, src) \
    asm volatile("cp.async.cg.shared.global [%0], [%1], 16;" :: "r"(dst), "l"(src))
#define CP_COMMIT() asm volatile("cp.async.commit_group;" ::: "memory")
#define CP_WAIT(n)  asm volatile("cp.async.wait_group %0;" :: "n"(n) : "memory")

// ---------------------------------------------------------------------------
// Prep: one-time bf16 hi/lo conversion of gathered emb (A) and W^T.
// ---------------------------------------------------------------------------
__global__ void __launch_bounds__(256) prep_kernel(
    const int* __restrict__ x, const float* __restrict__ emb,
    const float* __restrict__ W_f, const float* __restrict__ W_b)
{
    const size_t NA = (size_t)16384 * 256;
    const size_t NW = (size_t)2 * 2048 * 256;
    for (size_t i = (size_t)blockIdx.x * 256 + threadIdx.x; i < NA + NW;
         i += (size_t)gridDim.x * 256) {
        if (i < NA) {
            int r = (int)(i >> 8), k = (int)(i & 255);
            int tok = x[(r & 63) * TT + (r >> 6)];
            float v = emb[(size_t)tok * 256 + k];
            __nv_bfloat16 hb = __float2bfloat16(v);
            g_Ah[i] = hb;
            g_Al[i] = __float2bfloat16(v - __bfloat162float(hb));
        } else {
            size_t j = i - NA;
            int dir = (int)(j >> 19);
            int k = (int)((j >> 11) & 255), n = (int)(j & 2047);
            const float* Wm = dir ? W_b : W_f;
            float v = Wm[(size_t)k * 2048 + n];
            __nv_bfloat16 hb = __float2bfloat16(v);
            size_t o = ((size_t)dir * 2048 + n) * 256 + k;
            g_Wth[o] = hb;
            g_Wtl[o] = __float2bfloat16(v - __bfloat162float(hb));
        }
    }
}

// ---------------------------------------------------------------------------
// x_proj bf16 GEMM (pre-converted inputs). CTA: 128 rows x 256 cols. (R8)
// ---------------------------------------------------------------------------
__global__ void __launch_bounds__(128, 1) xproj_kernel(
    const float* __restrict__ b_f, const float* __restrict__ b_b)
{
    extern __shared__ char sp[];
    const int tid = threadIdx.x;
    const int warp = tid >> 5, lane = tid & 31;
    const int qr = lane >> 2, qc = lane & 3;
    const int dir = blockIdx.z;
    const int m0  = blockIdx.y << 7;
    const int ng  = blockIdx.x;
    const float* bs = dir ? b_b : b_f;
    float* sbias = (float*)(sp + BIAS_OFF);

    for (int i = tid; i < 256; i += 128) sbias[i] = bs[(ng << 8) + i];

    {
        const uint4* sh = (const uint4*)(g_Ah + (size_t)m0 * 256);
        const uint4* sl = (const uint4*)(g_Al + (size_t)m0 * 256);
        #pragma unroll 8
        for (int it = 0; it < 32; it++) {
            int f = (it << 7) + tid;
            int row = f >> 5, c = f & 31;
            *(uint4*)(sp + AH_OFF + row * 528 + c * 16) = sh[f];
            *(uint4*)(sp + AL_OFF + row * 528 + c * 16) = sl[f];
        }
    }

    const u32 spb = smem_u32(sp);
    u32 aAh[2], aAl[2];
    #pragma unroll
    for (int mi = 0; mi < 2; mi++) {
        int row = (warp << 5) + (mi << 4) + (lane & 15);
        aAh[mi] = spb + AH_OFF + row * 528 + (lane >> 4) * 16;
        aAl[mi] = spb + AL_OFF + row * 528 + (lane >> 4) * 16;
    }
    const int brow = (lane & 7) + 8 * (lane >> 4);
    const u32 koff = ((lane >> 3) & 1) * 16;
    float* gx = g_xproj + (size_t)dir * TT * 64 * 2048;

    for (int nt = 0; nt < 4; nt++) {
        const int ncol0 = (ng << 8) + (nt << 6);
        __syncthreads();
        {
            const uint4* wh = (const uint4*)(g_Wth + ((size_t)dir * 2048 + ncol0) * 256);
            const uint4* wl = (const uint4*)(g_Wtl + ((size_t)dir * 2048 + ncol0) * 256);
            #pragma unroll 4
            for (int it = 0; it < 16; it++) {
                int f = (it << 7) + tid;
                int row = f >> 5, c = f & 31;
                *(uint4*)(sp + WH_OFF + row * 528 + c * 16) = wh[f];
                *(uint4*)(sp + WL_OFF + row * 528 + c * 16) = wl[f];
            }
        }
        __syncthreads();

        float acc[2][8][4] = {};
        #pragma unroll 1
        for (int kk = 0; kk < 16; kk++) {
            u32 ah[2][4], al[2][4];
            LDSM4(ah[0], aAh[0] + kk * 32);
            LDSM4(ah[1], aAh[1] + kk * 32);
            LDSM4(al[0], aAl[0] + kk * 32);
            LDSM4(al[1], aAl[1] + kk * 32);
            #pragma unroll
            for (int p = 0; p < 4; p++) {
                u32 bh[4], bl[4];
                u32 ab = spb + (brow + (p << 4)) * 528 + koff + kk * 32;
                LDSM4(bh, ab + WH_OFF);
                LDSM4(bl, ab + WL_OFF);
                #pragma unroll
                for (int q = 0; q < 2; q++) {
                    int ni = (p << 1) + q;
                    #pragma unroll
                    for (int mi = 0; mi < 2; mi++) {
                        MMABF(acc[mi][ni], ah[mi], bh[2 * q], bh[2 * q + 1]);
                        MMABF(acc[mi][ni], ah[mi], bl[2 * q], bl[2 * q + 1]);
                        MMABF(acc[mi][ni], al[mi], bh[2 * q], bh[2 * q + 1]);
                    }
                }
            }
        }

        #pragma unroll
        for (int mi = 0; mi < 2; mi++) {
            int rl = (warp << 5) + (mi << 4) + qr;
            float* o0 = gx + (size_t)(m0 + rl) * 2048 + ncol0;
            float* o1 = gx + (size_t)(m0 + rl + 8) * 2048 + ncol0;
            #pragma unroll
            for (int ni = 0; ni < 8; ni++) {
                int cl = (ni << 3) + (qc << 1);
                float b0 = sbias[(nt << 6) + cl], b1 = sbias[(nt << 6) + cl + 1];
                *(float2*)(o0 + cl) = make_float2(acc[mi][ni][0] + b0, acc[mi][ni][1] + b1);
                *(float2*)(o1 + cl) = make_float2(acc[mi][ni][2] + b0, acc[mi][ni][3] + b1);
            }
        }
    }
}

// ---------------------------------------------------------------------------
// Persistent bidirectional LSTM scan. 128 CTAs x 256 thr (8 warps).
// h in single fp16 (64 KB restage); R as fp16 hi + 2^11-scaled fp16 lo in
// separate accumulators; warps = 4 m-tiles x 2 k-halves; per-dir barriers.
// ---------------------------------------------------------------------------
__global__ void __launch_bounds__(256, 1) scan_kernel(
    const int* __restrict__ x,
    const float* __restrict__ R_f,
    const float* __restrict__ R_b,
    float* __restrict__ out)
{
    extern __shared__ char sp[];
    const int tid = threadIdx.x;
    const int warp = tid >> 5, lane = tid & 31;
    const int qr = lane >> 2, qc = lane & 3;
    const int dir = blockIdx.x >> 6;
    const int ug  = blockIdx.x & 63;
    const int u0  = ug << 3;
    const float* Rm = dir ? R_b : R_f;
    const float* xp = g_xproj + (size_t)dir * TT * 64 * 2048;
    float* zr = (float*)(sp + ZB_OFF);
    u32* mbits = (u32*)(sp + MB_OFF);

    // Persistent B fp16: row n <- R[:, (n&3)*512 + u0 + (n>>2)]
    for (int i = tid; i < 32 * 512; i += 256) {
        int n = i & 31, k = i >> 5;
        float v = Rm[(size_t)k * 2048 + (n & 3) * 512 + u0 + (n >> 2)];
        __half hb = __float2half_rn(v);
        *(__half*)(sp + BH_OFF + n * 1040 + k * 2) = hb;
        *(__half*)(sp + BL_OFF + n * 1040 + k * 2) =
            __float2half_rn((v - __half2float(hb)) * 2048.0f);
    }
    // Mask bitmap: word w = t*2 + (b>>5)
    for (int w = tid; w < 512; w += 256) {
        int t = w >> 1, h32 = (w & 1) << 5;
        u32 bits = 0;
        #pragma unroll 8
        for (int j = 0; j < 32; j++)
            bits |= (u32)(x[(h32 + j) * TT + t] != 0) << j;
        mbits[w] = bits;
    }

    const u32 spb = smem_u32(sp);
    const int mtile = warp & 3, khalf = warp >> 2;
    const u32 aA = spb + HS_OFF + ((mtile << 4) + (lane & 15)) * 1040
                 + (lane >> 4) * 16 + khalf * 512;
    const int brow = (lane & 7) + 8 * (lane >> 4);
    const u32 koff = ((lane >> 3) & 1) * 16 + khalf * 512;

    const int ue = tid & 3;           // unit pair: units 2ue, 2ue+1
    const int be = tid >> 2;          // batch 0..63
    float cst[2] = {0.f, 0.f}, hcur[2] = {0.f, 0.f};
    unsigned* mybar = &g_bar2[dir][0];

    __syncthreads();

    for (int s = 0; s < TT; s++) {
        const int t = dir ? (TT - 1 - s) : s;
        const int m = (mbits[(t << 1) + (be >> 5)] >> (be & 31)) & 1;
        const float* xzp = xp + ((size_t)(t * 64 + be)) * 2048 + u0 + (ue << 1);
        float2 xg[4];
        #pragma unroll
        for (int g = 0; g < 4; g++) xg[g] = *(const float2*)(xzp + (g << 9));

        if (s) {
            // Restage h fp16: 64 rows x 64 uint4 = 64 KB
            const char* hb = (const char*)(g_hf16 +
                ((size_t)(((s - 1) & 1) * 2 + dir) * 64) * 512);
            #pragma unroll
            for (int it = 0; it < 16; it++) {
                int idx = (it << 8) + tid;          // 0..4095
                int row = idx >> 6;                 // 0..63
                int c = idx & 63;                   // uint4 col 0..63
                CP_ASYNC16(spb + HS_OFF + row * 1040 + c * 16,
                           hb + row * 1024 + c * 16);
            }
            CP_COMMIT();
            CP_WAIT(0);
            __syncthreads();

            float ah[4][4] = {}, al2[4][4] = {};
            #pragma unroll 2
            for (int kk = 0; kk < 16; kk++) {
                u32 a[4];
                LDSM4(a, aA + kk * 32);
                #pragma unroll
                for (int p = 0; p < 2; p++) {
                    u32 bh[4], bl[4];
                    u32 ab = spb + (brow + (p << 4)) * 1040 + koff + kk * 32;
                    LDSM4(bh, ab + BH_OFF);
                    LDSM4(bl, ab + BL_OFF);
                    MMAF16(ah[(p << 1) + 0], a, bh[0], bh[1]);
                    MMAF16(ah[(p << 1) + 1], a, bh[2], bh[3]);
                    MMAF16(al2[(p << 1) + 0], a, bl[0], bl[1]);
                    MMAF16(al2[(p << 1) + 1], a, bl[2], bl[3]);
                }
            }
            // Combine hi + lo*2^-11, write khalf partials (distinct rows/warp)
            {
                const float SC = 4.8828125e-4f;
                int r0 = (khalf << 6) + (mtile << 4) + qr;
                #pragma unroll
                for (int ni = 0; ni < 4; ni++) {
                    int col = (ni << 3) + (qc << 1);
                    *(float2*)(zr + r0 * 36 + col) = make_float2(
                        ah[ni][0] + al2[ni][0] * SC, ah[ni][1] + al2[ni][1] * SC);
                    *(float2*)(zr + (r0 + 8) * 36 + col) = make_float2(
                        ah[ni][2] + al2[ni][2] * SC, ah[ni][3] + al2[ni][3] * SC);
                }
            }
            __syncthreads();
        }

        float h2[2];
        #pragma unroll
        for (int j = 0; j < 2; j++) {
            int cb = ((ue << 1) + j) << 2;
            float zi = (j ? xg[0].y : xg[0].x), zf = (j ? xg[1].y : xg[1].x);
            float zg = (j ? xg[2].y : xg[2].x), zo = (j ? xg[3].y : xg[3].x);
            if (s) {
                float4 v0 = *(const float4*)(zr + be * 36 + cb);
                float4 v1 = *(const float4*)(zr + (64 + be) * 36 + cb);
                zi += v0.x + v1.x; zf += v0.y + v1.y;
                zg += v0.z + v1.z; zo += v0.w + v1.w;
            }
            float iv = tanhf(zi), fv = tanhf(zf), gv = tanhf(zg), ov = tanhf(zo);
            float cn = fv * cst[j] + iv * gv;
            float hn = ov * tanhf(cn);
            if (m) { cst[j] = cn; hcur[j] = hn; }
            h2[j] = hcur[j];
        }

        *(float2*)(out + (((size_t)(be * TT + t)) << 10) + (dir << 9) + u0 + (ue << 1)) =
            make_float2(h2[0], h2[1]);
        if (dir && s == TT - 1)
            *(float2*)(out + (size_t)64 * TT * 1024 + (size_t)be * 512 + u0 + (ue << 1)) =
                make_float2(h2[0], h2[1]);
        {
            __half2 hv = __floats2half2_rn(h2[0], h2[1]);
            __half* hb = g_hf16 + ((size_t)((s & 1) * 2 + dir) * 64) * 512;
            *(u32*)(hb + (size_t)be * 512 + u0 + (ue << 1)) = *(u32*)&hv;
        }

        __syncthreads();
        if (s < TT - 1) {
            if (tid == 0) {
                asm volatile("red.release.gpu.add.u32 [%0], 1;" :: "l"(mybar + s) : "memory");
                unsigned cnt;
                do {
                    asm volatile("ld.acquire.gpu.u32 %0, [%1];"
                                 : "=r"(cnt) : "l"(mybar + s) : "memory");
                } while (cnt < NB);
            }
            __syncthreads();
        }
    }

    // Self-reset this direction's barrier array for the next replay.
    __syncthreads();
    if (tid == 0) {
        asm volatile("red.release.gpu.add.u32 [%0], 1;" :: "l"(mybar + TT - 1) : "memory");
        if (ug == 0) {
            unsigned cnt;
            do {
                asm volatile("ld.acquire.gpu.u32 %0, [%1];"
                             : "=r"(cnt) : "l"(mybar + TT - 1) : "memory");
            } while (cnt < NB);
            for (int i = 0; i < TT; i++) mybar[i] = 0u;
        }
    }
}

extern "C" void kernel_launch(void* const* d_in, const int* in_sizes, int n_in,
                              void* d_out, int out_size) {
    const int*   x   = (const int*)d_in[0];
    const float* emb = (const float*)d_in[1];
    const float* W_f = (const float*)d_in[2];
    const float* R_f = (const float*)d_in[3];
    const float* b_f = (const float*)d_in[4];
    const float* W_b = (const float*)d_in[5];
    const float* R_b = (const float*)d_in[6];
    const float* b_b = (const float*)d_in[7];
    float* out = (float*)d_out;

    cudaFuncSetAttribute(xproj_kernel, cudaFuncAttributeMaxDynamicSharedMemorySize, SM_XP);
    cudaFuncSetAttribute(scan_kernel,  cudaFuncAttributeMaxDynamicSharedMemorySize, SM_SCAN);

    prep_kernel<<<2048, 256>>>(x, emb, W_f, W_b);
    xproj_kernel<<<dim3(8, 128, 2), 128, SM_XP>>>(b_f, b_b);
    scan_kernel<<<128, 256, SM_SCAN>>>(x, R_f, R_b, out);
}

// round 15
// speedup vs baseline: 1.6738x; 1.0060x over previous
#include <cuda_runtime.h>
#include <cuda_bf16.h>
#include <cuda_fp16.h>
#include <cstdint>
#include <cstddef>

typedef unsigned int u32;
typedef unsigned long long u64;

#define TT 256
#define NB 64            /* barrier quorum per direction */

// ---- scan smem layout (bytes) ----
#define HS_OFF 0          /* h fp16: 64 rows x 520 (1040 B/row) */
#define BH_OFF 66560      /* R_hi fp16: 32 n-rows x 520 */
#define BL_OFF 99840      /* R_lo fp16 (x2^11): 32 n-rows x 520 */
#define ZB_OFF 133120     /* z partials: 2 khalf x 64 x 36 f32 */
#define MB_OFF 151552     /* mask bitmap: 512 u32 */
#define SM_SCAN 153600

// ---- xproj smem layout ----
#define AH_OFF 0          /* A hi: 128 rows x 264 bf16 (528 B/row) */
#define AL_OFF 67584
#define WH_OFF 135168     /* W hi: 64 rows([n]) x 264 bf16 */
#define WL_OFF 168960
#define BIAS_OFF 202752
#define SM_XP 204800

// Device-global scratch (allocation-guard safe)
__device__ float          g_xproj[(size_t)2 * TT * 64 * 2048];  // [dir][t*64+b][2048]
__device__ __nv_bfloat16  g_Ah[(size_t)16384 * 256];            // emb gather hi
__device__ __nv_bfloat16  g_Al[(size_t)16384 * 256];
__device__ __nv_bfloat16  g_Wth[(size_t)2 * 2048 * 256];        // W^T hi: [dir][n][k]
__device__ __nv_bfloat16  g_Wtl[(size_t)2 * 2048 * 256];
__device__ __half         g_hf16[2 * 2 * 64 * 512];             // [par][dir][b][u] fp16
__device__ unsigned       g_bar2[2][TT];

__device__ __forceinline__ u32 smem_u32(const void* p) {
    u32 a;
    asm("{ .reg .u64 t; cvta.to.shared.u64 t, %1; cvt.u32.u64 %0, t; }" : "=r"(a) : "l"(p));
    return a;
}
__device__ __forceinline__ u32 packbf(float a, float b) {
    __nv_bfloat162 t = __floats2bfloat162_rn(a, b);
    return *reinterpret_cast<u32*>(&t);
}
__device__ __forceinline__ float tanh_ap(float x) {
    float r;
    asm("tanh.approx.f32 %0, %1;" : "=f"(r) : "f"(x));
    return r;
}

#define MMABF(d, a, b0_, b1_) \
    asm volatile( \
        "mma.sync.aligned.m16n8k16.row.col.f32.bf16.bf16.f32 " \
        "{%0,%1,%2,%3},{%4,%5,%6,%7},{%8,%9},{%0,%1,%2,%3};" \
        : "+f"((d)[0]), "+f"((d)[1]), "+f"((d)[2]), "+f"((d)[3]) \
        : "r"((a)[0]), "r"((a)[1]), "r"((a)[2]), "r"((a)[3]), \
          "r"(b0_), "r"(b1_))

#define MMAF16(d, a, b0_, b1_) \
    asm volatile( \
        "mma.sync.aligned.m16n8k16.row.col.f32.f16.f16.f32 " \
        "{%0,%1,%2,%3},{%4,%5,%6,%7},{%8,%9},{%0,%1,%2,%3};" \
        : "+f"((d)[0]), "+f"((d)[1]), "+f"((d)[2]), "+f"((d)[3]) \
        : "r"((a)[0]), "r"((a)[1]), "r"((a)[2]), "r"((a)[3]), \
          "r"(b0_), "r"(b1_))

#define LDSM4(r, a) \
    asm volatile("ldmatrix.sync.aligned.m8n8.x4.shared.b16 {%0,%1,%2,%3}, [%4];" \
        : "=r"((r)[0]), "=r"((r)[1]), "=r"((r)[2]), "=r"((r)[3]) : "r"(a))

#define CP_ASYNC16(dst, src) \
    asm volatile("cp.async.cg.shared.global [%0], [%1], 16;" :: "r"(dst), "l"(src))
#define CP_COMMIT() asm volatile("cp.async.commit_group;" ::: "memory")
#define CP_WAIT(n)  asm volatile("cp.async.wait_group %0;" :: "n"(n) : "memory")

// ---------------------------------------------------------------------------
// Prep: one-time bf16 hi/lo conversion of gathered emb (A) and W^T.
// ---------------------------------------------------------------------------
__global__ void __launch_bounds__(256) prep_kernel(
    const int* __restrict__ x, const float* __restrict__ emb,
    const float* __restrict__ W_f, const float* __restrict__ W_b)
{
    const size_t NA = (size_t)16384 * 256;
    const size_t NW = (size_t)2 * 2048 * 256;
    for (size_t i = (size_t)blockIdx.x * 256 + threadIdx.x; i < NA + NW;
         i += (size_t)gridDim.x * 256) {
        if (i < NA) {
            int r = (int)(i >> 8), k = (int)(i & 255);
            int tok = x[(r & 63) * TT + (r >> 6)];
            float v = emb[(size_t)tok * 256 + k];
            __nv_bfloat16 hb = __float2bfloat16(v);
            g_Ah[i] = hb;
            g_Al[i] = __float2bfloat16(v - __bfloat162float(hb));
        } else {
            size_t j = i - NA;
            int dir = (int)(j >> 19);
            int k = (int)((j >> 11) & 255), n = (int)(j & 2047);
            const float* Wm = dir ? W_b : W_f;
            float v = Wm[(size_t)k * 2048 + n];
            __nv_bfloat16 hb = __float2bfloat16(v);
            size_t o = ((size_t)dir * 2048 + n) * 256 + k;
            g_Wth[o] = hb;
            g_Wtl[o] = __float2bfloat16(v - __bfloat162float(hb));
        }
    }
}

// ---------------------------------------------------------------------------
// x_proj bf16 GEMM (pre-converted inputs). CTA: 128 rows x 256 cols. (R8)
// ---------------------------------------------------------------------------
__global__ void __launch_bounds__(128, 1) xproj_kernel(
    const float* __restrict__ b_f, const float* __restrict__ b_b)
{
    extern __shared__ char sp[];
    const int tid = threadIdx.x;
    const int warp = tid >> 5, lane = tid & 31;
    const int qr = lane >> 2, qc = lane & 3;
    const int dir = blockIdx.z;
    const int m0  = blockIdx.y << 7;
    const int ng  = blockIdx.x;
    const float* bs = dir ? b_b : b_f;
    float* sbias = (float*)(sp + BIAS_OFF);

    for (int i = tid; i < 256; i += 128) sbias[i] = bs[(ng << 8) + i];

    {
        const uint4* sh = (const uint4*)(g_Ah + (size_t)m0 * 256);
        const uint4* sl = (const uint4*)(g_Al + (size_t)m0 * 256);
        #pragma unroll 8
        for (int it = 0; it < 32; it++) {
            int f = (it << 7) + tid;
            int row = f >> 5, c = f & 31;
            *(uint4*)(sp + AH_OFF + row * 528 + c * 16) = sh[f];
            *(uint4*)(sp + AL_OFF + row * 528 + c * 16) = sl[f];
        }
    }

    const u32 spb = smem_u32(sp);
    u32 aAh[2], aAl[2];
    #pragma unroll
    for (int mi = 0; mi < 2; mi++) {
        int row = (warp << 5) + (mi << 4) + (lane & 15);
        aAh[mi] = spb + AH_OFF + row * 528 + (lane >> 4) * 16;
        aAl[mi] = spb + AL_OFF + row * 528 + (lane >> 4) * 16;
    }
    const int brow = (lane & 7) + 8 * (lane >> 4);
    const u32 koff = ((lane >> 3) & 1) * 16;
    float* gx = g_xproj + (size_t)dir * TT * 64 * 2048;

    for (int nt = 0; nt < 4; nt++) {
        const int ncol0 = (ng << 8) + (nt << 6);
        __syncthreads();
        {
            const uint4* wh = (const uint4*)(g_Wth + ((size_t)dir * 2048 + ncol0) * 256);
            const uint4* wl = (const uint4*)(g_Wtl + ((size_t)dir * 2048 + ncol0) * 256);
            #pragma unroll 4
            for (int it = 0; it < 16; it++) {
                int f = (it << 7) + tid;
                int row = f >> 5, c = f & 31;
                *(uint4*)(sp + WH_OFF + row * 528 + c * 16) = wh[f];
                *(uint4*)(sp + WL_OFF + row * 528 + c * 16) = wl[f];
            }
        }
        __syncthreads();

        float acc[2][8][4] = {};
        #pragma unroll 1
        for (int kk = 0; kk < 16; kk++) {
            u32 ah[2][4], al[2][4];
            LDSM4(ah[0], aAh[0] + kk * 32);
            LDSM4(ah[1], aAh[1] + kk * 32);
            LDSM4(al[0], aAl[0] + kk * 32);
            LDSM4(al[1], aAl[1] + kk * 32);
            #pragma unroll
            for (int p = 0; p < 4; p++) {
                u32 bh[4], bl[4];
                u32 ab = spb + (brow + (p << 4)) * 528 + koff + kk * 32;
                LDSM4(bh, ab + WH_OFF);
                LDSM4(bl, ab + WL_OFF);
                #pragma unroll
                for (int q = 0; q < 2; q++) {
                    int ni = (p << 1) + q;
                    #pragma unroll
                    for (int mi = 0; mi < 2; mi++) {
                        MMABF(acc[mi][ni], ah[mi], bh[2 * q], bh[2 * q + 1]);
                        MMABF(acc[mi][ni], ah[mi], bl[2 * q], bl[2 * q + 1]);
                        MMABF(acc[mi][ni], al[mi], bh[2 * q], bh[2 * q + 1]);
                    }
                }
            }
        }

        #pragma unroll
        for (int mi = 0; mi < 2; mi++) {
            int rl = (warp << 5) + (mi << 4) + qr;
            float* o0 = gx + (size_t)(m0 + rl) * 2048 + ncol0;
            float* o1 = gx + (size_t)(m0 + rl + 8) * 2048 + ncol0;
            #pragma unroll
            for (int ni = 0; ni < 8; ni++) {
                int cl = (ni << 3) + (qc << 1);
                float b0 = sbias[(nt << 6) + cl], b1 = sbias[(nt << 6) + cl + 1];
                *(float2*)(o0 + cl) = make_float2(acc[mi][ni][0] + b0, acc[mi][ni][1] + b1);
                *(float2*)(o1 + cl) = make_float2(acc[mi][ni][2] + b0, acc[mi][ni][3] + b1);
            }
        }
    }
}

// ---------------------------------------------------------------------------
// Persistent bidirectional LSTM scan. 128 CTAs x 256 thr (8 warps).
// h in single fp16; R as fp16 hi + 2^11-scaled fp16 lo; 4 m-tiles x 2
// k-halves; per-dir barriers; HW tanh.approx gates.
// ---------------------------------------------------------------------------
__global__ void __launch_bounds__(256, 1) scan_kernel(
    const int* __restrict__ x,
    const float* __restrict__ R_f,
    const float* __restrict__ R_b,
    float* __restrict__ out)
{
    extern __shared__ char sp[];
    const int tid = threadIdx.x;
    const int warp = tid >> 5, lane = tid & 31;
    const int qr = lane >> 2, qc = lane & 3;
    const int dir = blockIdx.x >> 6;
    const int ug  = blockIdx.x & 63;
    const int u0  = ug << 3;
    const float* Rm = dir ? R_b : R_f;
    const float* xp = g_xproj + (size_t)dir * TT * 64 * 2048;
    float* zr = (float*)(sp + ZB_OFF);
    u32* mbits = (u32*)(sp + MB_OFF);

    // Persistent B fp16: row n <- R[:, (n&3)*512 + u0 + (n>>2)]
    for (int i = tid; i < 32 * 512; i += 256) {
        int n = i & 31, k = i >> 5;
        float v = Rm[(size_t)k * 2048 + (n & 3) * 512 + u0 + (n >> 2)];
        __half hb = __float2half_rn(v);
        *(__half*)(sp + BH_OFF + n * 1040 + k * 2) = hb;
        *(__half*)(sp + BL_OFF + n * 1040 + k * 2) =
            __float2half_rn((v - __half2float(hb)) * 2048.0f);
    }
    // Mask bitmap: word w = t*2 + (b>>5)
    for (int w = tid; w < 512; w += 256) {
        int t = w >> 1, h32 = (w & 1) << 5;
        u32 bits = 0;
        #pragma unroll 8
        for (int j = 0; j < 32; j++)
            bits |= (u32)(x[(h32 + j) * TT + t] != 0) << j;
        mbits[w] = bits;
    }

    const u32 spb = smem_u32(sp);
    const int mtile = warp & 3, khalf = warp >> 2;
    const u32 aA = spb + HS_OFF + ((mtile << 4) + (lane & 15)) * 1040
                 + (lane >> 4) * 16 + khalf * 512;
    const int brow = (lane & 7) + 8 * (lane >> 4);
    const u32 koff = ((lane >> 3) & 1) * 16 + khalf * 512;

    const int ue = tid & 3;           // unit pair: units 2ue, 2ue+1
    const int be = tid >> 2;          // batch 0..63
    float cst[2] = {0.f, 0.f}, hcur[2] = {0.f, 0.f};
    unsigned* mybar = &g_bar2[dir][0];

    __syncthreads();

    for (int s = 0; s < TT; s++) {
        const int t = dir ? (TT - 1 - s) : s;
        const int m = (mbits[(t << 1) + (be >> 5)] >> (be & 31)) & 1;
        const float* xzp = xp + ((size_t)(t * 64 + be)) * 2048 + u0 + (ue << 1);
        float2 xg[4];
        #pragma unroll
        for (int g = 0; g < 4; g++) xg[g] = *(const float2*)(xzp + (g << 9));

        if (s) {
            // Restage h fp16: 64 rows x 64 uint4 = 64 KB
            const char* hb = (const char*)(g_hf16 +
                ((size_t)(((s - 1) & 1) * 2 + dir) * 64) * 512);
            #pragma unroll
            for (int it = 0; it < 16; it++) {
                int idx = (it << 8) + tid;          // 0..4095
                int row = idx >> 6;                 // 0..63
                int c = idx & 63;                   // uint4 col 0..63
                CP_ASYNC16(spb + HS_OFF + row * 1040 + c * 16,
                           hb + row * 1024 + c * 16);
            }
            CP_COMMIT();
            CP_WAIT(0);
            __syncthreads();

            float ah[4][4] = {}, al2[4][4] = {};
            #pragma unroll 2
            for (int kk = 0; kk < 16; kk++) {
                u32 a[4];
                LDSM4(a, aA + kk * 32);
                #pragma unroll
                for (int p = 0; p < 2; p++) {
                    u32 bh[4], bl[4];
                    u32 ab = spb + (brow + (p << 4)) * 1040 + koff + kk * 32;
                    LDSM4(bh, ab + BH_OFF);
                    LDSM4(bl, ab + BL_OFF);
                    MMAF16(ah[(p << 1) + 0], a, bh[0], bh[1]);
                    MMAF16(ah[(p << 1) + 1], a, bh[2], bh[3]);
                    MMAF16(al2[(p << 1) + 0], a, bl[0], bl[1]);
                    MMAF16(al2[(p << 1) + 1], a, bl[2], bl[3]);
                }
            }
            // Combine hi + lo*2^-11, write khalf partials (distinct rows/warp)
            {
                const float SC = 4.8828125e-4f;
                int r0 = (khalf << 6) + (mtile << 4) + qr;
                #pragma unroll
                for (int ni = 0; ni < 4; ni++) {
                    int col = (ni << 3) + (qc << 1);
                    *(float2*)(zr + r0 * 36 + col) = make_float2(
                        ah[ni][0] + al2[ni][0] * SC, ah[ni][1] + al2[ni][1] * SC);
                    *(float2*)(zr + (r0 + 8) * 36 + col) = make_float2(
                        ah[ni][2] + al2[ni][2] * SC, ah[ni][3] + al2[ni][3] * SC);
                }
            }
            __syncthreads();
        }

        float h2[2];
        #pragma unroll
        for (int j = 0; j < 2; j++) {
            int cb = ((ue << 1) + j) << 2;
            float zi = (j ? xg[0].y : xg[0].x), zf = (j ? xg[1].y : xg[1].x);
            float zg = (j ? xg[2].y : xg[2].x), zo = (j ? xg[3].y : xg[3].x);
            if (s) {
                float4 v0 = *(const float4*)(zr + be * 36 + cb);
                float4 v1 = *(const float4*)(zr + (64 + be) * 36 + cb);
                zi += v0.x + v1.x; zf += v0.y + v1.y;
                zg += v0.z + v1.z; zo += v0.w + v1.w;
            }
            float iv = tanh_ap(zi), fv = tanh_ap(zf);
            float gv = tanh_ap(zg), ov = tanh_ap(zo);
            float cn = fv * cst[j] + iv * gv;
            float hn = ov * tanh_ap(cn);
            if (m) { cst[j] = cn; hcur[j] = hn; }
            h2[j] = hcur[j];
        }

        *(float2*)(out + (((size_t)(be * TT + t)) << 10) + (dir << 9) + u0 + (ue << 1)) =
            make_float2(h2[0], h2[1]);
        if (dir && s == TT - 1)
            *(float2*)(out + (size_t)64 * TT * 1024 + (size_t)be * 512 + u0 + (ue << 1)) =
                make_float2(h2[0], h2[1]);
        {
            __half2 hv = __floats2half2_rn(h2[0], h2[1]);
            __half* hb = g_hf16 + ((size_t)((s & 1) * 2 + dir) * 64) * 512;
            *(u32*)(hb + (size_t)be * 512 + u0 + (ue << 1)) = *(u32*)&hv;
        }

        __syncthreads();
        if (s < TT - 1) {
            if (tid == 0) {
                asm volatile("red.release.gpu.add.u32 [%0], 1;" :: "l"(mybar + s) : "memory");
                unsigned cnt;
                do {
                    asm volatile("ld.acquire.gpu.u32 %0, [%1];"
                                 : "=r"(cnt) : "l"(mybar + s) : "memory");
                } while (cnt < NB);
            }
            __syncthreads();
        }
    }

    // Self-reset this direction's barrier array for the next replay.
    __syncthreads();
    if (tid == 0) {
        asm volatile("red.release.gpu.add.u32 [%0], 1;" :: "l"(mybar + TT - 1) : "memory");
        if (ug == 0) {
            unsigned cnt;
            do {
                asm volatile("ld.acquire.gpu.u32 %0, [%1];"
                             : "=r"(cnt) : "l"(mybar + TT - 1) : "memory");
            } while (cnt < NB);
            for (int i = 0; i < TT; i++) mybar[i] = 0u;
        }
    }
}

extern "C" void kernel_launch(void* const* d_in, const int* in_sizes, int n_in,
                              void* d_out, int out_size) {
    const int*   x   = (const int*)d_in[0];
    const float* emb = (const float*)d_in[1];
    const float* W_f = (const float*)d_in[2];
    const float* R_f = (const float*)d_in[3];
    const float* b_f = (const float*)d_in[4];
    const float* W_b = (const float*)d_in[5];
    const float* R_b = (const float*)d_in[6];
    const float* b_b = (const float*)d_in[7];
    float* out = (float*)d_out;

    cudaFuncSetAttribute(xproj_kernel, cudaFuncAttributeMaxDynamicSharedMemorySize, SM_XP);
    cudaFuncSetAttribute(scan_kernel,  cudaFuncAttributeMaxDynamicSharedMemorySize, SM_SCAN);

    prep_kernel<<<2048, 256>>>(x, emb, W_f, W_b);
    xproj_kernel<<<dim3(8, 128, 2), 128, SM_XP>>>(b_f, b_b);
    scan_kernel<<<128, 256, SM_SCAN>>>(x, R_f, R_b, out);
}

// round 16
// speedup vs baseline: 1.7390x; 1.0389x over previous
#include <cuda_runtime.h>
#include <cuda_bf16.h>
#include <cuda_fp16.h>
#include <cstdint>
#include <cstddef>

typedef unsigned int u32;
typedef unsigned long long u64;

#define TT 256
#define NB 64            /* barrier quorum per direction */

// ---- scan smem layout (bytes) ----
#define HS_OFF 0          /* h fp16: 64 rows x 520 (1040 B/row) */
#define BH_OFF 66560      /* R_hi fp16: 32 n-rows x 520 */
#define BL_OFF 99840      /* R_lo fp16 (x2^11): 32 n-rows x 520 */
#define ZB_OFF 133120     /* z partials: 2 khalf x 64 x 36 f32 */
#define MB_OFF 151552     /* mask bitmap: 512 u32 */
#define SM_SCAN 153600

// ---- xproj smem layout ----
#define AH_OFF 0          /* A hi: 128 rows x 264 bf16 (528 B/row) */
#define AL_OFF 67584
#define WH_OFF 135168     /* W hi: 64 rows([n]) x 264 bf16 */
#define WL_OFF 168960
#define BIAS_OFF 202752
#define SM_XP 204800

// Device-global scratch (allocation-guard safe)
__device__ float          g_xproj[(size_t)2 * TT * 64 * 2048];  // [dir][t*64+b][2048]
__device__ __nv_bfloat16  g_Ah[(size_t)16384 * 256];            // emb gather hi
__device__ __nv_bfloat16  g_Al[(size_t)16384 * 256];
__device__ __nv_bfloat16  g_Wth[(size_t)2 * 2048 * 256];        // W^T hi: [dir][n][k]
__device__ __nv_bfloat16  g_Wtl[(size_t)2 * 2048 * 256];
__device__ __half         g_hf16[2 * 2 * 64 * 512];             // [par][dir][b][u] fp16
__device__ unsigned       g_bar2[2][TT];

__device__ __forceinline__ u32 smem_u32(const void* p) {
    u32 a;
    asm("{ .reg .u64 t; cvta.to.shared.u64 t, %1; cvt.u32.u64 %0, t; }" : "=r"(a) : "l"(p));
    return a;
}
__device__ __forceinline__ u32 packbf(float a, float b) {
    __nv_bfloat162 t = __floats2bfloat162_rn(a, b);
    return *reinterpret_cast<u32*>(&t);
}
__device__ __forceinline__ float tanh_ap(float x) {
    float r;
    asm("tanh.approx.f32 %0, %1;" : "=f"(r) : "f"(x));
    return r;
}

#define MMABF(d, a, b0_, b1_) \
    asm volatile( \
        "mma.sync.aligned.m16n8k16.row.col.f32.bf16.bf16.f32 " \
        "{%0,%1,%2,%3},{%4,%5,%6,%7},{%8,%9},{%0,%1,%2,%3};" \
        : "+f"((d)[0]), "+f"((d)[1]), "+f"((d)[2]), "+f"((d)[3]) \
        : "r"((a)[0]), "r"((a)[1]), "r"((a)[2]), "r"((a)[3]), \
          "r"(b0_), "r"(b1_))

#define MMAF16(d, a, b0_, b1_) \
    asm volatile( \
        "mma.sync.aligned.m16n8k16.row.col.f32.f16.f16.f32 " \
        "{%0,%1,%2,%3},{%4,%5,%6,%7},{%8,%9},{%0,%1,%2,%3};" \
        : "+f"((d)[0]), "+f"((d)[1]), "+f"((d)[2]), "+f"((d)[3]) \
        : "r"((a)[0]), "r"((a)[1]), "r"((a)[2]), "r"((a)[3]), \
          "r"(b0_), "r"(b1_))

#define LDSM4(r, a) \
    asm volatile("ldmatrix.sync.aligned.m8n8.x4.shared.b16 {%0,%1,%2,%3}, [%4];" \
        : "=r"((r)[0]), "=r"((r)[1]), "=r"((r)[2]), "=r"((r)[3]) : "r"(a))

#define CP_ASYNC16(dst, src) \
    asm volatile("cp.async.cg.shared.global [%0], [%1], 16;" :: "r"(dst), "l"(src))
#define CP_COMMIT() asm volatile("cp.async.commit_group;" ::: "memory")
#define CP_WAIT(n)  asm volatile("cp.async.wait_group %0;" :: "n"(n) : "memory")

// ---------------------------------------------------------------------------
// Prep: one-time bf16 hi/lo conversion of gathered emb (A) and W^T.
// ---------------------------------------------------------------------------
__global__ void __launch_bounds__(256) prep_kernel(
    const int* __restrict__ x, const float* __restrict__ emb,
    const float* __restrict__ W_f, const float* __restrict__ W_b)
{
    const size_t NA = (size_t)16384 * 256;
    const size_t NW = (size_t)2 * 2048 * 256;
    for (size_t i = (size_t)blockIdx.x * 256 + threadIdx.x; i < NA + NW;
         i += (size_t)gridDim.x * 256) {
        if (i < NA) {
            int r = (int)(i >> 8), k = (int)(i & 255);
            int tok = x[(r & 63) * TT + (r >> 6)];
            float v = emb[(size_t)tok * 256 + k];
            __nv_bfloat16 hb = __float2bfloat16(v);
            g_Ah[i] = hb;
            g_Al[i] = __float2bfloat16(v - __bfloat162float(hb));
        } else {
            size_t j = i - NA;
            int dir = (int)(j >> 19);
            int k = (int)((j >> 11) & 255), n = (int)(j & 2047);
            const float* Wm = dir ? W_b : W_f;
            float v = Wm[(size_t)k * 2048 + n];
            __nv_bfloat16 hb = __float2bfloat16(v);
            size_t o = ((size_t)dir * 2048 + n) * 256 + k;
            g_Wth[o] = hb;
            g_Wtl[o] = __float2bfloat16(v - __bfloat162float(hb));
        }
    }
}

// ---------------------------------------------------------------------------
// x_proj bf16 GEMM. CTA: 128 rows x 256 cols, 256 threads (8 warps).
// Warp = ONE 16-row m-tile (2 warps/SMSP for latency hiding).
// ---------------------------------------------------------------------------
__global__ void __launch_bounds__(256, 1) xproj_kernel(
    const float* __restrict__ b_f, const float* __restrict__ b_b)
{
    extern __shared__ char sp[];
    const int tid = threadIdx.x;
    const int warp = tid >> 5, lane = tid & 31;
    const int qr = lane >> 2, qc = lane & 3;
    const int dir = blockIdx.z;
    const int m0  = blockIdx.y << 7;
    const int ng  = blockIdx.x;
    const float* bs = dir ? b_b : b_f;
    float* sbias = (float*)(sp + BIAS_OFF);

    if (tid < 256) sbias[tid] = bs[(ng << 8) + tid];

    {
        const uint4* sh = (const uint4*)(g_Ah + (size_t)m0 * 256);
        const uint4* sl = (const uint4*)(g_Al + (size_t)m0 * 256);
        #pragma unroll 8
        for (int it = 0; it < 16; it++) {
            int f = (it << 8) + tid;               // 0..4095
            int row = f >> 5, c = f & 31;
            *(uint4*)(sp + AH_OFF + row * 528 + c * 16) = sh[f];
            *(uint4*)(sp + AL_OFF + row * 528 + c * 16) = sl[f];
        }
    }

    const u32 spb = smem_u32(sp);
    u32 aAh, aAl;
    {
        int row = (warp << 4) + (lane & 15);
        aAh = spb + AH_OFF + row * 528 + (lane >> 4) * 16;
        aAl = spb + AL_OFF + row * 528 + (lane >> 4) * 16;
    }
    const int brow = (lane & 7) + 8 * (lane >> 4);
    const u32 koff = ((lane >> 3) & 1) * 16;
    float* gx = g_xproj + (size_t)dir * TT * 64 * 2048;

    for (int nt = 0; nt < 4; nt++) {
        const int ncol0 = (ng << 8) + (nt << 6);
        __syncthreads();
        {
            const uint4* wh = (const uint4*)(g_Wth + ((size_t)dir * 2048 + ncol0) * 256);
            const uint4* wl = (const uint4*)(g_Wtl + ((size_t)dir * 2048 + ncol0) * 256);
            #pragma unroll 4
            for (int it = 0; it < 8; it++) {
                int f = (it << 8) + tid;           // 0..2047
                int row = f >> 5, c = f & 31;
                *(uint4*)(sp + WH_OFF + row * 528 + c * 16) = wh[f];
                *(uint4*)(sp + WL_OFF + row * 528 + c * 16) = wl[f];
            }
        }
        __syncthreads();

        float acc[8][4] = {};
        #pragma unroll 1
        for (int kk = 0; kk < 16; kk++) {
            u32 ah[4], al[4];
            LDSM4(ah, aAh + kk * 32);
            LDSM4(al, aAl + kk * 32);
            #pragma unroll
            for (int p = 0; p < 4; p++) {
                u32 bh[4], bl[4];
                u32 ab = spb + (brow + (p << 4)) * 528 + koff + kk * 32;
                LDSM4(bh, ab + WH_OFF);
                LDSM4(bl, ab + WL_OFF);
                #pragma unroll
                for (int q = 0; q < 2; q++) {
                    int ni = (p << 1) + q;
                    MMABF(acc[ni], ah, bh[2 * q], bh[2 * q + 1]);
                    MMABF(acc[ni], ah, bl[2 * q], bl[2 * q + 1]);
                    MMABF(acc[ni], al, bh[2 * q], bh[2 * q + 1]);
                }
            }
        }

        {
            int rl = (warp << 4) + qr;
            float* o0 = gx + (size_t)(m0 + rl) * 2048 + ncol0;
            float* o1 = gx + (size_t)(m0 + rl + 8) * 2048 + ncol0;
            #pragma unroll
            for (int ni = 0; ni < 8; ni++) {
                int cl = (ni << 3) + (qc << 1);
                float b0 = sbias[(nt << 6) + cl], b1 = sbias[(nt << 6) + cl + 1];
                *(float2*)(o0 + cl) = make_float2(acc[ni][0] + b0, acc[ni][1] + b1);
                *(float2*)(o1 + cl) = make_float2(acc[ni][2] + b0, acc[ni][3] + b1);
            }
        }
    }
}

// ---------------------------------------------------------------------------
// Persistent bidirectional LSTM scan. 128 CTAs x 256 thr (8 warps).
// h in single fp16; R as fp16 hi + 2^11-scaled fp16 lo; 4 m-tiles x 2
// k-halves; per-dir barriers; HW tanh.approx gates.  (identical to R15)
// ---------------------------------------------------------------------------
__global__ void __launch_bounds__(256, 1) scan_kernel(
    const int* __restrict__ x,
    const float* __restrict__ R_f,
    const float* __restrict__ R_b,
    float* __restrict__ out)
{
    extern __shared__ char sp[];
    const int tid = threadIdx.x;
    const int warp = tid >> 5, lane = tid & 31;
    const int qr = lane >> 2, qc = lane & 3;
    const int dir = blockIdx.x >> 6;
    const int ug  = blockIdx.x & 63;
    const int u0  = ug << 3;
    const float* Rm = dir ? R_b : R_f;
    const float* xp = g_xproj + (size_t)dir * TT * 64 * 2048;
    float* zr = (float*)(sp + ZB_OFF);
    u32* mbits = (u32*)(sp + MB_OFF);

    // Persistent B fp16: row n <- R[:, (n&3)*512 + u0 + (n>>2)]
    for (int i = tid; i < 32 * 512; i += 256) {
        int n = i & 31, k = i >> 5;
        float v = Rm[(size_t)k * 2048 + (n & 3) * 512 + u0 + (n >> 2)];
        __half hb = __float2half_rn(v);
        *(__half*)(sp + BH_OFF + n * 1040 + k * 2) = hb;
        *(__half*)(sp + BL_OFF + n * 1040 + k * 2) =
            __float2half_rn((v - __half2float(hb)) * 2048.0f);
    }
    // Mask bitmap: word w = t*2 + (b>>5)
    for (int w = tid; w < 512; w += 256) {
        int t = w >> 1, h32 = (w & 1) << 5;
        u32 bits = 0;
        #pragma unroll 8
        for (int j = 0; j < 32; j++)
            bits |= (u32)(x[(h32 + j) * TT + t] != 0) << j;
        mbits[w] = bits;
    }

    const u32 spb = smem_u32(sp);
    const int mtile = warp & 3, khalf = warp >> 2;
    const u32 aA = spb + HS_OFF + ((mtile << 4) + (lane & 15)) * 1040
                 + (lane >> 4) * 16 + khalf * 512;
    const int brow = (lane & 7) + 8 * (lane >> 4);
    const u32 koff = ((lane >> 3) & 1) * 16 + khalf * 512;

    const int ue = tid & 3;           // unit pair: units 2ue, 2ue+1
    const int be = tid >> 2;          // batch 0..63
    float cst[2] = {0.f, 0.f}, hcur[2] = {0.f, 0.f};
    unsigned* mybar = &g_bar2[dir][0];

    __syncthreads();

    for (int s = 0; s < TT; s++) {
        const int t = dir ? (TT - 1 - s) : s;
        const int m = (mbits[(t << 1) + (be >> 5)] >> (be & 31)) & 1;
        const float* xzp = xp + ((size_t)(t * 64 + be)) * 2048 + u0 + (ue << 1);
        float2 xg[4];
        #pragma unroll
        for (int g = 0; g < 4; g++) xg[g] = *(const float2*)(xzp + (g << 9));

        if (s) {
            // Restage h fp16: 64 rows x 64 uint4 = 64 KB
            const char* hb = (const char*)(g_hf16 +
                ((size_t)(((s - 1) & 1) * 2 + dir) * 64) * 512);
            #pragma unroll
            for (int it = 0; it < 16; it++) {
                int idx = (it << 8) + tid;          // 0..4095
                int row = idx >> 6;                 // 0..63
                int c = idx & 63;                   // uint4 col 0..63
                CP_ASYNC16(spb + HS_OFF + row * 1040 + c * 16,
                           hb + row * 1024 + c * 16);
            }
            CP_COMMIT();
            CP_WAIT(0);
            __syncthreads();

            float ah[4][4] = {}, al2[4][4] = {};
            #pragma unroll 2
            for (int kk = 0; kk < 16; kk++) {
                u32 a[4];
                LDSM4(a, aA + kk * 32);
                #pragma unroll
                for (int p = 0; p < 2; p++) {
                    u32 bh[4], bl[4];
                    u32 ab = spb + (brow + (p << 4)) * 1040 + koff + kk * 32;
                    LDSM4(bh, ab + BH_OFF);
                    LDSM4(bl, ab + BL_OFF);
                    MMAF16(ah[(p << 1) + 0], a, bh[0], bh[1]);
                    MMAF16(ah[(p << 1) + 1], a, bh[2], bh[3]);
                    MMAF16(al2[(p << 1) + 0], a, bl[0], bl[1]);
                    MMAF16(al2[(p << 1) + 1], a, bl[2], bl[3]);
                }
            }
            // Combine hi + lo*2^-11, write khalf partials (distinct rows/warp)
            {
                const float SC = 4.8828125e-4f;
                int r0 = (khalf << 6) + (mtile << 4) + qr;
                #pragma unroll
                for (int ni = 0; ni < 4; ni++) {
                    int col = (ni << 3) + (qc << 1);
                    *(float2*)(zr + r0 * 36 + col) = make_float2(
                        ah[ni][0] + al2[ni][0] * SC, ah[ni][1] + al2[ni][1] * SC);
                    *(float2*)(zr + (r0 + 8) * 36 + col) = make_float2(
                        ah[ni][2] + al2[ni][2] * SC, ah[ni][3] + al2[ni][3] * SC);
                }
            }
            __syncthreads();
        }

        float h2[2];
        #pragma unroll
        for (int j = 0; j < 2; j++) {
            int cb = ((ue << 1) + j) << 2;
            float zi = (j ? xg[0].y : xg[0].x), zf = (j ? xg[1].y : xg[1].x);
            float zg = (j ? xg[2].y : xg[2].x), zo = (j ? xg[3].y : xg[3].x);
            if (s) {
                float4 v0 = *(const float4*)(zr + be * 36 + cb);
                float4 v1 = *(const float4*)(zr + (64 + be) * 36 + cb);
                zi += v0.x + v1.x; zf += v0.y + v1.y;
                zg += v0.z + v1.z; zo += v0.w + v1.w;
            }
            float iv = tanh_ap(zi), fv = tanh_ap(zf);
            float gv = tanh_ap(zg), ov = tanh_ap(zo);
            float cn = fv * cst[j] + iv * gv;
            float hn = ov * tanh_ap(cn);
            if (m) { cst[j] = cn; hcur[j] = hn; }
            h2[j] = hcur[j];
        }

        *(float2*)(out + (((size_t)(be * TT + t)) << 10) + (dir << 9) + u0 + (ue << 1)) =
            make_float2(h2[0], h2[1]);
        if (dir && s == TT - 1)
            *(float2*)(out + (size_t)64 * TT * 1024 + (size_t)be * 512 + u0 + (ue << 1)) =
                make_float2(h2[0], h2[1]);
        {
            __half2 hv = __floats2half2_rn(h2[0], h2[1]);
            __half* hb = g_hf16 + ((size_t)((s & 1) * 2 + dir) * 64) * 512;
            *(u32*)(hb + (size_t)be * 512 + u0 + (ue << 1)) = *(u32*)&hv;
        }

        __syncthreads();
        if (s < TT - 1) {
            if (tid == 0) {
                asm volatile("red.release.gpu.add.u32 [%0], 1;" :: "l"(mybar + s) : "memory");
                unsigned cnt;
                do {
                    asm volatile("ld.acquire.gpu.u32 %0, [%1];"
                                 : "=r"(cnt) : "l"(mybar + s) : "memory");
                } while (cnt < NB);
            }
            __syncthreads();
        }
    }

    // Self-reset this direction's barrier array for the next replay.
    __syncthreads();
    if (tid == 0) {
        asm volatile("red.release.gpu.add.u32 [%0], 1;" :: "l"(mybar + TT - 1) : "memory");
        if (ug == 0) {
            unsigned cnt;
            do {
                asm volatile("ld.acquire.gpu.u32 %0, [%1];"
                             : "=r"(cnt) : "l"(mybar + TT - 1) : "memory");
            } while (cnt < NB);
            for (int i = 0; i < TT; i++) mybar[i] = 0u;
        }
    }
}

extern "C" void kernel_launch(void* const* d_in, const int* in_sizes, int n_in,
                              void* d_out, int out_size) {
    const int*   x   = (const int*)d_in[0];
    const float* emb = (const float*)d_in[1];
    const float* W_f = (const float*)d_in[2];
    const float* R_f = (const float*)d_in[3];
    const float* b_f = (const float*)d_in[4];
    const float* W_b = (const float*)d_in[5];
    const float* R_b = (const float*)d_in[6];
    const float* b_b = (const float*)d_in[7];
    float* out = (float*)d_out;

    cudaFuncSetAttribute(xproj_kernel, cudaFuncAttributeMaxDynamicSharedMemorySize, SM_XP);
    cudaFuncSetAttribute(scan_kernel,  cudaFuncAttributeMaxDynamicSharedMemorySize, SM_SCAN);

    prep_kernel<<<2048, 256>>>(x, emb, W_f, W_b);
    xproj_kernel<<<dim3(8, 128, 2), 256, SM_XP>>>(b_f, b_b);
    scan_kernel<<<128, 256, SM_SCAN>>>(x, R_f, R_b, out);
}

// round 17
// speedup vs baseline: 1.7889x; 1.0287x over previous
#include <cuda_runtime.h>
#include <cuda_bf16.h>
#include <cuda_fp16.h>
#include <cstdint>
#include <cstddef>

typedef unsigned int u32;
typedef unsigned long long u64;

#define TT 256
#define NB 64            /* CTAs per direction */

// ---- scan smem layout (bytes) ----
#define HS_OFF 0          /* h fp16: 64 rows x 520 (1040 B/row) */
#define BH_OFF 66560      /* R_hi fp16: 32 n-rows x 520 */
#define BL_OFF 99840      /* R_lo fp16 (x2^11): 32 n-rows x 520 */
#define ZB_OFF 133120     /* z partials: 2 khalf x 64 x 36 f32 */
#define MB_OFF 151552     /* mask bitmap: 512 u32 */
#define SM_SCAN 153600

// ---- xproj smem layout ----
#define AH_OFF 0          /* A hi: 128 rows x 264 bf16 (528 B/row) */
#define AL_OFF 67584
#define WH_OFF 135168     /* W hi: 64 rows([n]) x 264 bf16 */
#define WL_OFF 168960
#define BIAS_OFF 202752
#define SM_XP 204800

// Device-global scratch (allocation-guard safe)
__device__ float          g_xproj[(size_t)2 * TT * 64 * 2048];  // [dir][t*64+b][2048]
__device__ __nv_bfloat16  g_Ah[(size_t)16384 * 256];            // emb gather hi
__device__ __nv_bfloat16  g_Al[(size_t)16384 * 256];
__device__ __nv_bfloat16  g_Wth[(size_t)2 * 2048 * 256];        // W^T hi: [dir][n][k]
__device__ __nv_bfloat16  g_Wtl[(size_t)2 * 2048 * 256];
__device__ __half         g_hf16[4 * 2 * 64 * 512];             // [par&3][dir][b][u] fp16
__device__ u32            g_flg[2][64][256];                    // [dir][producer][step]
__device__ unsigned       g_bar2[2][2];                         // end barrier slots

__device__ __forceinline__ u32 smem_u32(const void* p) {
    u32 a;
    asm("{ .reg .u64 t; cvta.to.shared.u64 t, %1; cvt.u32.u64 %0, t; }" : "=r"(a) : "l"(p));
    return a;
}
__device__ __forceinline__ float tanh_ap(float x) {
    float r;
    asm("tanh.approx.f32 %0, %1;" : "=f"(r) : "f"(x));
    return r;
}

#define MMABF(d, a, b0_, b1_) \
    asm volatile( \
        "mma.sync.aligned.m16n8k16.row.col.f32.bf16.bf16.f32 " \
        "{%0,%1,%2,%3},{%4,%5,%6,%7},{%8,%9},{%0,%1,%2,%3};" \
        : "+f"((d)[0]), "+f"((d)[1]), "+f"((d)[2]), "+f"((d)[3]) \
        : "r"((a)[0]), "r"((a)[1]), "r"((a)[2]), "r"((a)[3]), \
          "r"(b0_), "r"(b1_))

#define MMAF16(d, a, b0_, b1_) \
    asm volatile( \
        "mma.sync.aligned.m16n8k16.row.col.f32.f16.f16.f32 " \
        "{%0,%1,%2,%3},{%4,%5,%6,%7},{%8,%9},{%0,%1,%2,%3};" \
        : "+f"((d)[0]), "+f"((d)[1]), "+f"((d)[2]), "+f"((d)[3]) \
        : "r"((a)[0]), "r"((a)[1]), "r"((a)[2]), "r"((a)[3]), \
          "r"(b0_), "r"(b1_))

#define LDSM4(r, a) \
    asm volatile("ldmatrix.sync.aligned.m8n8.x4.shared.b16 {%0,%1,%2,%3}, [%4];" \
        : "=r"((r)[0]), "=r"((r)[1]), "=r"((r)[2]), "=r"((r)[3]) : "r"(a))

#define CP_ASYNC16(dst, src) \
    asm volatile("cp.async.cg.shared.global [%0], [%1], 16;" :: "r"(dst), "l"(src))
#define CP_COMMIT() asm volatile("cp.async.commit_group;" ::: "memory")
#define CP_WAIT(n)  asm volatile("cp.async.wait_group %0;" :: "n"(n) : "memory")

// ---------------------------------------------------------------------------
// Prep: one-time bf16 hi/lo conversion of gathered emb (A) and W^T.
// ---------------------------------------------------------------------------
__global__ void __launch_bounds__(256) prep_kernel(
    const int* __restrict__ x, const float* __restrict__ emb,
    const float* __restrict__ W_f, const float* __restrict__ W_b)
{
    const size_t NA = (size_t)16384 * 256;
    const size_t NW = (size_t)2 * 2048 * 256;
    for (size_t i = (size_t)blockIdx.x * 256 + threadIdx.x; i < NA + NW;
         i += (size_t)gridDim.x * 256) {
        if (i < NA) {
            int r = (int)(i >> 8), k = (int)(i & 255);
            int tok = x[(r & 63) * TT + (r >> 6)];
            float v = emb[(size_t)tok * 256 + k];
            __nv_bfloat16 hb = __float2bfloat16(v);
            g_Ah[i] = hb;
            g_Al[i] = __float2bfloat16(v - __bfloat162float(hb));
        } else {
            size_t j = i - NA;
            int dir = (int)(j >> 19);
            int k = (int)((j >> 11) & 255), n = (int)(j & 2047);
            const float* Wm = dir ? W_b : W_f;
            float v = Wm[(size_t)k * 2048 + n];
            __nv_bfloat16 hb = __float2bfloat16(v);
            size_t o = ((size_t)dir * 2048 + n) * 256 + k;
            g_Wth[o] = hb;
            g_Wtl[o] = __float2bfloat16(v - __bfloat162float(hb));
        }
    }
}

// ---------------------------------------------------------------------------
// x_proj bf16 GEMM. CTA: 128 rows x 256 cols, 256 threads (8 warps). (R16)
// ---------------------------------------------------------------------------
__global__ void __launch_bounds__(256, 1) xproj_kernel(
    const float* __restrict__ b_f, const float* __restrict__ b_b)
{
    extern __shared__ char sp[];
    const int tid = threadIdx.x;
    const int warp = tid >> 5, lane = tid & 31;
    const int qr = lane >> 2, qc = lane & 3;
    const int dir = blockIdx.z;
    const int m0  = blockIdx.y << 7;
    const int ng  = blockIdx.x;
    const float* bs = dir ? b_b : b_f;
    float* sbias = (float*)(sp + BIAS_OFF);

    sbias[tid] = bs[(ng << 8) + tid];

    {
        const uint4* sh = (const uint4*)(g_Ah + (size_t)m0 * 256);
        const uint4* sl = (const uint4*)(g_Al + (size_t)m0 * 256);
        #pragma unroll 8
        for (int it = 0; it < 16; it++) {
            int f = (it << 8) + tid;
            int row = f >> 5, c = f & 31;
            *(uint4*)(sp + AH_OFF + row * 528 + c * 16) = sh[f];
            *(uint4*)(sp + AL_OFF + row * 528 + c * 16) = sl[f];
        }
    }

    const u32 spb = smem_u32(sp);
    u32 aAh, aAl;
    {
        int row = (warp << 4) + (lane & 15);
        aAh = spb + AH_OFF + row * 528 + (lane >> 4) * 16;
        aAl = spb + AL_OFF + row * 528 + (lane >> 4) * 16;
    }
    const int brow = (lane & 7) + 8 * (lane >> 4);
    const u32 koff = ((lane >> 3) & 1) * 16;
    float* gx = g_xproj + (size_t)dir * TT * 64 * 2048;

    for (int nt = 0; nt < 4; nt++) {
        const int ncol0 = (ng << 8) + (nt << 6);
        __syncthreads();
        {
            const uint4* wh = (const uint4*)(g_Wth + ((size_t)dir * 2048 + ncol0) * 256);
            const uint4* wl = (const uint4*)(g_Wtl + ((size_t)dir * 2048 + ncol0) * 256);
            #pragma unroll 4
            for (int it = 0; it < 8; it++) {
                int f = (it << 8) + tid;
                int row = f >> 5, c = f & 31;
                *(uint4*)(sp + WH_OFF + row * 528 + c * 16) = wh[f];
                *(uint4*)(sp + WL_OFF + row * 528 + c * 16) = wl[f];
            }
        }
        __syncthreads();

        float acc[8][4] = {};
        #pragma unroll 1
        for (int kk = 0; kk < 16; kk++) {
            u32 ah[4], al[4];
            LDSM4(ah, aAh + kk * 32);
            LDSM4(al, aAl + kk * 32);
            #pragma unroll
            for (int p = 0; p < 4; p++) {
                u32 bh[4], bl[4];
                u32 ab = spb + (brow + (p << 4)) * 528 + koff + kk * 32;
                LDSM4(bh, ab + WH_OFF);
                LDSM4(bl, ab + WL_OFF);
                #pragma unroll
                for (int q = 0; q < 2; q++) {
                    int ni = (p << 1) + q;
                    MMABF(acc[ni], ah, bh[2 * q], bh[2 * q + 1]);
                    MMABF(acc[ni], ah, bl[2 * q], bl[2 * q + 1]);
                    MMABF(acc[ni], al, bh[2 * q], bh[2 * q + 1]);
                }
            }
        }

        {
            int rl = (warp << 4) + qr;
            float* o0 = gx + (size_t)(m0 + rl) * 2048 + ncol0;
            float* o1 = gx + (size_t)(m0 + rl + 8) * 2048 + ncol0;
            #pragma unroll
            for (int ni = 0; ni < 8; ni++) {
                int cl = (ni << 3) + (qc << 1);
                float b0 = sbias[(nt << 6) + cl], b1 = sbias[(nt << 6) + cl + 1];
                *(float2*)(o0 + cl) = make_float2(acc[ni][0] + b0, acc[ni][1] + b1);
                *(float2*)(o1 + cl) = make_float2(acc[ni][2] + b0, acc[ni][3] + b1);
            }
        }
    }
}

// ---------------------------------------------------------------------------
// Persistent bidirectional LSTM scan, 128 CTAs x 256 thr.
// Barrier-free dataflow: per-producer flags + per-column cp.async pull;
// h in 4-deep parity ring (skew bound 1 step => parities distinct mod 4).
// ---------------------------------------------------------------------------
__global__ void __launch_bounds__(256, 1) scan_kernel(
    const int* __restrict__ x,
    const float* __restrict__ R_f,
    const float* __restrict__ R_b,
    float* __restrict__ out)
{
    extern __shared__ char sp[];
    const int tid = threadIdx.x;
    const int warp = tid >> 5, lane = tid & 31;
    const int qr = lane >> 2, qc = lane & 3;
    const int dir = blockIdx.x >> 6;
    const int ug  = blockIdx.x & 63;
    const int u0  = ug << 3;
    const float* Rm = dir ? R_b : R_f;
    const float* xp = g_xproj + (size_t)dir * TT * 64 * 2048;
    float* zr = (float*)(sp + ZB_OFF);
    u32* mbits = (u32*)(sp + MB_OFF);

    // Persistent B fp16: row n <- R[:, (n&3)*512 + u0 + (n>>2)]
    for (int i = tid; i < 32 * 512; i += 256) {
        int n = i & 31, k = i >> 5;
        float v = Rm[(size_t)k * 2048 + (n & 3) * 512 + u0 + (n >> 2)];
        __half hb = __float2half_rn(v);
        *(__half*)(sp + BH_OFF + n * 1040 + k * 2) = hb;
        *(__half*)(sp + BL_OFF + n * 1040 + k * 2) =
            __float2half_rn((v - __half2float(hb)) * 2048.0f);
    }
    // Mask bitmap: word w = t*2 + (b>>5)
    for (int w = tid; w < 512; w += 256) {
        int t = w >> 1, h32 = (w & 1) << 5;
        u32 bits = 0;
        #pragma unroll 8
        for (int j = 0; j < 32; j++)
            bits |= (u32)(x[(h32 + j) * TT + t] != 0) << j;
        mbits[w] = bits;
    }

    const u32 spb = smem_u32(sp);
    const int mtile = warp & 3, khalf = warp >> 2;
    const u32 aA = spb + HS_OFF + ((mtile << 4) + (lane & 15)) * 1040
                 + (lane >> 4) * 16 + khalf * 512;
    const int brow = (lane & 7) + 8 * (lane >> 4);
    const u32 koff = ((lane >> 3) & 1) * 16 + khalf * 512;

    const int ue = tid & 3;           // unit pair: units 2ue, 2ue+1
    const int be = tid >> 2;          // batch 0..63
    const int jprod = tid & 63;       // producer column this thread pulls
    const u32* myflg = &g_flg[dir][jprod][0];
    float cst[2] = {0.f, 0.f}, hcur[2] = {0.f, 0.f};

    __syncthreads();

    for (int s = 0; s < TT; s++) {
        const int t = dir ? (TT - 1 - s) : s;
        const int m = (mbits[(t << 1) + (be >> 5)] >> (be & 31)) & 1;
        const float* xzp = xp + ((size_t)(t * 64 + be)) * 2048 + u0 + (ue << 1);
        float2 xg[4];
        #pragma unroll
        for (int g = 0; g < 4; g++) xg[g] = *(const float2*)(xzp + (g << 9));

        if (s) {
            // Pull-based restage: wait only for producer jprod, then copy its
            // 16-byte piece of each of 16 rows (rows (it<<2)+(tid>>6)).
            {
                u32 f;
                do {
                    asm volatile("ld.acquire.gpu.u32 %0, [%1];"
                                 : "=r"(f) : "l"(myflg + (s - 1)) : "memory");
                } while (!f);
            }
            const char* hb = (const char*)(g_hf16 +
                ((size_t)(((s - 1) & 3) * 2 + dir) * 64) * 512);
            #pragma unroll
            for (int it = 0; it < 16; it++) {
                int row = (it << 2) + (tid >> 6);
                CP_ASYNC16(spb + HS_OFF + row * 1040 + jprod * 16,
                           hb + row * 1024 + jprod * 16);
            }
            CP_COMMIT();
            CP_WAIT(0);
            __syncthreads();

            float ah[4][4] = {}, al2[4][4] = {};
            #pragma unroll 2
            for (int kk = 0; kk < 16; kk++) {
                u32 a[4];
                LDSM4(a, aA + kk * 32);
                #pragma unroll
                for (int p = 0; p < 2; p++) {
                    u32 bh[4], bl[4];
                    u32 ab = spb + (brow + (p << 4)) * 1040 + koff + kk * 32;
                    LDSM4(bh, ab + BH_OFF);
                    LDSM4(bl, ab + BL_OFF);
                    MMAF16(ah[(p << 1) + 0], a, bh[0], bh[1]);
                    MMAF16(ah[(p << 1) + 1], a, bh[2], bh[3]);
                    MMAF16(al2[(p << 1) + 0], a, bl[0], bl[1]);
                    MMAF16(al2[(p << 1) + 1], a, bl[2], bl[3]);
                }
            }
            {
                const float SC = 4.8828125e-4f;
                int r0 = (khalf << 6) + (mtile << 4) + qr;
                #pragma unroll
                for (int ni = 0; ni < 4; ni++) {
                    int col = (ni << 3) + (qc << 1);
                    *(float2*)(zr + r0 * 36 + col) = make_float2(
                        ah[ni][0] + al2[ni][0] * SC, ah[ni][1] + al2[ni][1] * SC);
                    *(float2*)(zr + (r0 + 8) * 36 + col) = make_float2(
                        ah[ni][2] + al2[ni][2] * SC, ah[ni][3] + al2[ni][3] * SC);
                }
            }
            __syncthreads();
        }

        float h2[2];
        #pragma unroll
        for (int j = 0; j < 2; j++) {
            int cb = ((ue << 1) + j) << 2;
            float zi = (j ? xg[0].y : xg[0].x), zf = (j ? xg[1].y : xg[1].x);
            float zg = (j ? xg[2].y : xg[2].x), zo = (j ? xg[3].y : xg[3].x);
            if (s) {
                float4 v0 = *(const float4*)(zr + be * 36 + cb);
                float4 v1 = *(const float4*)(zr + (64 + be) * 36 + cb);
                zi += v0.x + v1.x; zf += v0.y + v1.y;
                zg += v0.z + v1.z; zo += v0.w + v1.w;
            }
            float iv = tanh_ap(zi), fv = tanh_ap(zf);
            float gv = tanh_ap(zg), ov = tanh_ap(zo);
            float cn = fv * cst[j] + iv * gv;
            float hn = ov * tanh_ap(cn);
            if (m) { cst[j] = cn; hcur[j] = hn; }
            h2[j] = hcur[j];
        }

        *(float2*)(out + (((size_t)(be * TT + t)) << 10) + (dir << 9) + u0 + (ue << 1)) =
            make_float2(h2[0], h2[1]);
        if (dir && s == TT - 1)
            *(float2*)(out + (size_t)64 * TT * 1024 + (size_t)be * 512 + u0 + (ue << 1)) =
                make_float2(h2[0], h2[1]);
        {
            __half2 hv = __floats2half2_rn(h2[0], h2[1]);
            __half* hb = g_hf16 + ((size_t)((s & 3) * 2 + dir) * 64) * 512;
            *(u32*)(hb + (size_t)be * 512 + u0 + (ue << 1)) = *(u32*)&hv;
        }

        __syncthreads();     // all h-slice stores done (h.b. for release below)
        if (s < TT - 1) {
            if (tid == 0)
                asm volatile("red.release.gpu.add.u32 [%0], 1;"
                             :: "l"(&g_flg[dir][ug][s]) : "memory");
        }
    }

    // ---- End: two-phase quorum, then reset own flags for next replay ----
    if (tid == 0) {
        asm volatile("red.release.gpu.add.u32 [%0], 1;" :: "l"(&g_bar2[dir][0]) : "memory");
        unsigned cnt;
        do {
            asm volatile("ld.acquire.gpu.u32 %0, [%1];"
                         : "=r"(cnt) : "l"(&g_bar2[dir][0]) : "memory");
        } while (cnt < NB);
    }
    __syncthreads();
    g_flg[dir][ug][tid] = 0u;           // all 256 steps reset by 256 threads
    __syncthreads();
    if (tid == 0) {
        asm volatile("red.release.gpu.add.u32 [%0], 1;" :: "l"(&g_bar2[dir][1]) : "memory");
        if (ug == 0) {
            unsigned cnt;
            do {
                asm volatile("ld.acquire.gpu.u32 %0, [%1];"
                             : "=r"(cnt) : "l"(&g_bar2[dir][1]) : "memory");
            } while (cnt < NB);
            g_bar2[dir][0] = 0u;
            g_bar2[dir][1] = 0u;
        }
    }
}

extern "C" void kernel_launch(void* const* d_in, const int* in_sizes, int n_in,
                              void* d_out, int out_size) {
    const int*   x   = (const int*)d_in[0];
    const float* emb = (const float*)d_in[1];
    const float* W_f = (const float*)d_in[2];
    const float* R_f = (const float*)d_in[3];
    const float* b_f = (const float*)d_in[4];
    const float* W_b = (const float*)d_in[5];
    const float* R_b = (const float*)d_in[6];
    const float* b_b = (const float*)d_in[7];
    float* out = (float*)d_out;

    cudaFuncSetAttribute(xproj_kernel, cudaFuncAttributeMaxDynamicSharedMemorySize, SM_XP);
    cudaFuncSetAttribute(scan_kernel,  cudaFuncAttributeMaxDynamicSharedMemorySize, SM_SCAN);

    prep_kernel<<<2048, 256>>>(x, emb, W_f, W_b);
    xproj_kernel<<<dim3(8, 128, 2), 256, SM_XP>>>(b_f, b_b);
    scan_kernel<<<128, 256, SM_SCAN>>>(x, R_f, R_b, out);
}